// round 12
// baseline (speedup 1.0000x reference)
#include <cuda_runtime.h>
#include <cstddef>
#include <cstdint>

#define VOCABN 50000
#define DIMN   300
#define HN     100
#define TN     512
#define BN     256
#define OUTN   3
#define G4     400   // 4*H
#define G4P    512   // padded N (4 tiles of 128)
#define KP0    304   // padded K for layer-0 table GEMM (emb K=300)
#define KP1    112   // padded K for xg GEMMs (h K=100)

// ---------------- scratch (static device globals; no allocation) ----------------
__device__ float g_table[(size_t)VOCABN * G4];
__device__ float g_xg[(size_t)BN * TN * G4];
__device__ float g_h[(size_t)BN * TN * HN];
__device__ float g_hlast[BN * HN];
__device__ int   g_order[BN];
__device__ float g_w0p[(size_t)G4P * KP0];
__device__ float g_w1p[(size_t)G4P * KP1];
__device__ float g_w2p[(size_t)G4P * KP1];

// ---------------- packed f32x2 helpers ----------------
typedef unsigned long long ull;

__device__ __forceinline__ ull pack2(float x, float y) {
    ull r;
    asm("mov.b64 %0, {%1, %2};" : "=l"(r) : "f"(x), "f"(y));
    return r;
}
__device__ __forceinline__ void unpack2(ull v, float& x, float& y) {
    asm("mov.b64 {%0, %1}, %2;" : "=f"(x), "=f"(y) : "l"(v));
}
__device__ __forceinline__ ull fma2(ull a, ull b, ull c) {
    ull d;
    asm("fma.rn.f32x2 %0, %1, %2, %3;" : "=l"(d) : "l"(a), "l"(b), "l"(c));
    return d;
}

// ---------------- tf32 helpers ----------------
__device__ __forceinline__ uint32_t f2tf(float x) {
    uint32_t r;
    asm("cvt.rna.tf32.f32 %0, %1;" : "=r"(r) : "f"(x));
    return r;
}
__device__ __forceinline__ void cvt_hl(float v, uint32_t& h, uint32_t& l) {
    h = f2tf(v);
    float lo = v - __uint_as_float(h);
    l = f2tf(lo);
}
__device__ __forceinline__ void mma_tf32(float (&d)[4], const uint32_t (&a)[4], const uint32_t (&b)[2]) {
    asm volatile(
        "mma.sync.aligned.m16n8k8.row.col.f32.tf32.tf32.f32 "
        "{%0,%1,%2,%3}, {%4,%5,%6,%7}, {%8,%9}, {%0,%1,%2,%3};"
        : "+f"(d[0]), "+f"(d[1]), "+f"(d[2]), "+f"(d[3])
        : "r"(a[0]), "r"(a[1]), "r"(a[2]), "r"(a[3]), "r"(b[0]), "r"(b[1]));
}

// ---------------- prep: sort + all weight padding in one launch ----------------
__global__ void prep(const int* __restrict__ lengths, int* __restrict__ order,
                     const float* __restrict__ w0, float* __restrict__ w0p,
                     const float* __restrict__ w1, float* __restrict__ w1p,
                     const float* __restrict__ w2s, float* __restrict__ w2p)
{
    const int bx = blockIdx.x;
    if (bx == 0) {
        __shared__ int ls[BN];
        int b = threadIdx.x;
        ls[b] = lengths[b];
        __syncthreads();
        int len = ls[b];
        int rank = 0;
#pragma unroll 8
        for (int jj = 0; jj < BN; jj++) {
            int lj = ls[jj];
            rank += (lj > len) || (lj == len && jj < b);
        }
        order[rank] = b;
        return;
    }
    int idx = (bx - 1) * 256 + threadIdx.x;
    const int n0 = G4P * KP0, n1 = G4P * KP1;
    if (idx < n0) {
        int r = idx / KP0, kk = idx % KP0;
        w0p[idx] = (r < G4 && kk < DIMN) ? w0[r * DIMN + kk] : 0.f;
        return;
    }
    idx -= n0;
    if (idx < n1) {
        int r = idx / KP1, kk = idx % KP1;
        w1p[idx] = (r < G4 && kk < HN) ? w1[r * HN + kk] : 0.f;
        return;
    }
    idx -= n1;
    if (idx < n1) {
        int r = idx / KP1, kk = idx % KP1;
        w2p[idx] = (r < G4 && kk < HN) ? w2s[r * HN + kk] : 0.f;
    }
}

// ---------------- 3xTF32 tensor-core GEMM, 128x128 CTA tile ----------------
// C[m,n] = sum_k A[m,k]*Bp[n,k] + bias1[n] + bias2[n],  N fixed = 400.
// 256 threads = 8 warps (4m x 2n), warp tile 32x64 -> mma:LDS ratio 2x round-9.
// smem pitch-20 (bank-exact), single buffer. B fragments loaded in chunks of 4.
template<int SKIP>
__global__ void __launch_bounds__(256)
gemm_tf32(const float* __restrict__ A, int M, int Ks, int Kreal,
          const float* __restrict__ Bp, int Kp,
          const float* __restrict__ bias1, const float* __restrict__ bias2,
          const int* __restrict__ lengths, float* __restrict__ C)
{
    const int N = G4;
    const int m0 = blockIdx.y * 128;
    const int n0 = blockIdx.x * 128;
    if (SKIP) {
        int b  = m0 / TN;
        int t0 = m0 % TN;
        if (t0 >= lengths[b]) return;
    }

    __shared__ uint32_t As_hi[128 * 20], As_lo[128 * 20];
    __shared__ uint32_t Bs_hi[128 * 20], Bs_lo[128 * 20];
    __shared__ float bias_s[128];

    const int tid  = threadIdx.x;
    const int wid  = tid >> 5;
    const int lane = tid & 31;
    const int wm   = wid & 3;       // 4 m positions of 32
    const int wn   = wid >> 2;      // 2 n positions of 64
    const int gid  = lane >> 2;
    const int tq   = lane & 3;

    if (tid < 128) {
        int n = n0 + tid;
        bias_s[tid] = (n < N) ? bias1[n] + bias2[n] : 0.f;
    }

    // staging coords: A and B both 2 float4 / thread (128 rows x 4 quads each)
    int mA[2], kqA[2];
#pragma unroll
    for (int i = 0; i < 2; i++) { int f = i * 256 + tid; mA[i] = f >> 2; kqA[i] = (f & 3) * 4; }

    const float* aP[2];
    const float* bP[2];
#pragma unroll
    for (int i = 0; i < 2; i++) {
        int mg = m0 + mA[i]; if (mg > M - 1) mg = M - 1;
        aP[i] = A + (size_t)mg * Ks;
        bP[i] = Bp + (size_t)(n0 + mA[i]) * Kp;   // padded rows, no clamp needed
    }

    float acc[2][8][4];
#pragma unroll
    for (int i = 0; i < 2; i++)
#pragma unroll
        for (int j = 0; j < 8; j++)
#pragma unroll
            for (int q = 0; q < 4; q++) acc[i][j][q] = 0.f;

    const int kcl = Kreal - 4;
    float4 ra[2], rb[2];
#pragma unroll
    for (int i = 0; i < 2; i++) {
        int kk = kqA[i]; if (kk > kcl) kk = kcl;
        ra[i] = *reinterpret_cast<const float4*>(aP[i] + kk);
        rb[i] = *reinterpret_cast<const float4*>(bP[i] + kqA[i]);
    }

    for (int k0 = 0; k0 < Kp; k0 += 16) {
        // ---- stage regs -> smem (cvt to tf32 hi/lo) ----
#pragma unroll
        for (int i = 0; i < 2; i++) {
            uint32_t h0, l0, h1, l1, h2, l2, h3, l3;
            cvt_hl(ra[i].x, h0, l0); cvt_hl(ra[i].y, h1, l1);
            cvt_hl(ra[i].z, h2, l2); cvt_hl(ra[i].w, h3, l3);
            int off = mA[i] * 20 + kqA[i];
            *reinterpret_cast<uint4*>(&As_hi[off]) = make_uint4(h0, h1, h2, h3);
            *reinterpret_cast<uint4*>(&As_lo[off]) = make_uint4(l0, l1, l2, l3);
            cvt_hl(rb[i].x, h0, l0); cvt_hl(rb[i].y, h1, l1);
            cvt_hl(rb[i].z, h2, l2); cvt_hl(rb[i].w, h3, l3);
            *reinterpret_cast<uint4*>(&Bs_hi[off]) = make_uint4(h0, h1, h2, h3);
            *reinterpret_cast<uint4*>(&Bs_lo[off]) = make_uint4(l0, l1, l2, l3);
        }
        __syncthreads();

        // ---- prefetch next stage ----
        int k0n = k0 + 16;
        if (k0n < Kp) {
#pragma unroll
            for (int i = 0; i < 2; i++) {
                int kk = k0n + kqA[i]; if (kk > kcl) kk = kcl;
                ra[i] = *reinterpret_cast<const float4*>(aP[i] + kk);
                rb[i] = *reinterpret_cast<const float4*>(bP[i] + k0n + kqA[i]);
            }
        }

        // ---- mma over 2 k-steps of 8 ----
#pragma unroll
        for (int ks = 0; ks < 2; ks++) {
            const int kb = ks * 8;
            uint32_t ah[2][4], al[2][4];
#pragma unroll
            for (int mf = 0; mf < 2; mf++) {
                int base = (wm * 32 + mf * 16 + gid) * 20 + kb + tq;
                ah[mf][0] = As_hi[base];              al[mf][0] = As_lo[base];
                ah[mf][1] = As_hi[base + 8 * 20];     al[mf][1] = As_lo[base + 8 * 20];
                ah[mf][2] = As_hi[base + 4];          al[mf][2] = As_lo[base + 4];
                ah[mf][3] = As_hi[base + 8 * 20 + 4]; al[mf][3] = As_lo[base + 8 * 20 + 4];
            }
            // B fragments in chunks of 4 (register pressure)
#pragma unroll
            for (int nfc = 0; nfc < 2; nfc++) {
                uint32_t bh[4][2], bl[4][2];
#pragma unroll
                for (int nf = 0; nf < 4; nf++) {
                    int base = (wn * 64 + (nfc * 4 + nf) * 8 + gid) * 20 + kb + tq;
                    bh[nf][0] = Bs_hi[base];     bl[nf][0] = Bs_lo[base];
                    bh[nf][1] = Bs_hi[base + 4]; bl[nf][1] = Bs_lo[base + 4];
                }
#pragma unroll
                for (int mf = 0; mf < 2; mf++)
#pragma unroll
                    for (int nf = 0; nf < 4; nf++) {
                        mma_tf32(acc[mf][nfc * 4 + nf], ah[mf], bh[nf]);
                        mma_tf32(acc[mf][nfc * 4 + nf], ah[mf], bl[nf]);
                        mma_tf32(acc[mf][nfc * 4 + nf], al[mf], bh[nf]);
                    }
            }
        }
        __syncthreads();
    }

    // ---- epilogue ----
#pragma unroll
    for (int mf = 0; mf < 2; mf++) {
#pragma unroll
        for (int nf = 0; nf < 8; nf++) {
            int row0 = m0 + wm * 32 + mf * 16 + gid;
            int cb   = wn * 64 + nf * 8 + 2 * tq;
            int col  = n0 + cb;
            if (col < N) {
                float b0v = bias_s[cb], b1v = bias_s[cb + 1];
                if (row0 < M) {
                    float2 v = make_float2(acc[mf][nf][0] + b0v, acc[mf][nf][1] + b1v);
                    *reinterpret_cast<float2*>(&C[(size_t)row0 * N + col]) = v;
                }
                int row1 = row0 + 8;
                if (row1 < M) {
                    float2 v = make_float2(acc[mf][nf][2] + b0v, acc[mf][nf][3] + b1v);
                    *reinterpret_cast<float2*>(&C[(size_t)row1 * N + col]) = v;
                }
            }
        }
    }
}

// ---------------- LSTM scan (round-11 winner, unchanged) ----------------
__device__ __forceinline__ float tanh_(float x) {
    return 2.f * __fdividef(1.f, 1.f + __expf(-2.f * x)) - 1.f;
}

// thread tid = j*4 + g : hidden unit j (0..99), gate g (0=i,1=f,2=g,3=o)
template<int MODE>
__global__ void __launch_bounds__(400, 1)
lstm_scan(const float* __restrict__ xg,
          const int* __restrict__ xtok,
          const int* __restrict__ lengths,
          const int* __restrict__ order,
          const float* __restrict__ w_hh,     // [400,100]
          float* __restrict__ h_out,          // [B,T,100]
          float* __restrict__ hlast)          // [B,100]
{
    const int b   = order[blockIdx.x];
    const int tid = threadIdx.x;
    const int j   = tid >> 2;
    const int g   = tid & 3;
    const int r   = g * 100 + j;

    __shared__ __align__(16) float h_s[2][104];
    __shared__ int idx_s[TN];

    const int len = lengths[b];

    if (MODE == 0) {
        for (int t = tid; t < TN; t += 400) idx_s[t] = xtok[b * TN + t];
    }

    ull w2[50];
    {
        const ull* wrow = reinterpret_cast<const ull*>(w_hh + r * 100);
#pragma unroll
        for (int q = 0; q < 50; q++) w2[q] = wrow[q];
    }

    if (tid < 100) h_s[0][tid] = 0.f;
    float c = 0.f;
    __syncthreads();

    const bool is_t = (g == 2);
    const bool gsel = (g & 2) != 0;

    const float* xp = (MODE == 0) ? nullptr : xg + ((size_t)b * TN) * G4 + r;
    float xg_next;
    if (MODE == 0) xg_next = xg[(size_t)idx_s[0] * G4 + r];
    else           xg_next = *xp;

    for (int t = 0; t < len; t++) {
        float xv = xg_next;
        if (t + 1 < len) {
            if (MODE == 0) {
                xg_next = xg[(size_t)idx_s[t + 1] * G4 + r];
            } else {
                xp += G4;
                xg_next = *xp;
            }
        }
        const ulonglong2* h2 = reinterpret_cast<const ulonglong2*>(h_s[t & 1]);

        ull acc0 = pack2(xv, 0.f);
        ull acc1 = 0ULL;
#pragma unroll
        for (int q = 0; q < 25; q++) {
            ulonglong2 hh = h2[q];
            acc0 = fma2(hh.x, w2[2 * q],     acc0);
            acc1 = fma2(hh.y, w2[2 * q + 1], acc1);
        }
        float a0, a1, a2, a3;
        unpack2(acc0, a0, a1);
        unpack2(acc1, a2, a3);
        float acc = (a0 + a1) + (a2 + a3);

        float z = is_t ? 2.f * acc : acc;
        float s = __fdividef(1.f, 1.f + __expf(-z));
        float gate = is_t ? (2.f * s - 1.f) : s;

        float v1 = __shfl_xor_sync(0xFFFFFFFFu, gate, 1);
        float pa = (g & 1) ? v1 : gate;
        float pb = (g & 1) ? gate : v1;
        float qa = __shfl_xor_sync(0xFFFFFFFFu, pa, 2);
        float qb = __shfl_xor_sync(0xFFFFFFFFu, pb, 2);
        float ig = gsel ? qa : pa;
        float gg = gsel ? pa : qa;
        float fg = gsel ? qb : pb;
        float og = gsel ? pb : qb;

        c = fg * c + ig * gg;
        float hn = og * tanh_(c);
        if (g == 0) {
            h_s[(t + 1) & 1][j] = hn;
            if (MODE != 2) h_out[((size_t)b * TN + t) * HN + j] = hn;
        }
        if (MODE == 2 && g == 0 && t == len - 1) hlast[b * HN + j] = hn;
        __syncthreads();
    }
}

// ---------------- head ----------------
__global__ void head_kernel(const float* __restrict__ hlast,
                            const float* __restrict__ w_fc,
                            const float* __restrict__ b_fc,
                            float* __restrict__ out)
{
    int b = blockIdx.x * blockDim.x + threadIdx.x;
    if (b >= BN) return;
#pragma unroll
    for (int o = 0; o < OUTN; o++) {
        float s = b_fc[o];
#pragma unroll
        for (int k = 0; k < HN; k++)
            s += hlast[b * HN + k] * w_fc[o * HN + k];
        out[b * OUTN + o] = s;
    }
}

// ---------------- launch (single stream) ----------------
extern "C" void kernel_launch(void* const* d_in, const int* in_sizes, int n_in,
                              void* d_out, int out_size)
{
    const int*   x      = (const int*)d_in[0];
    const int*   lens   = (const int*)d_in[1];
    const float* emb    = (const float*)d_in[2];
    const float* w_ih0  = (const float*)d_in[3];
    const float* w_hh0  = (const float*)d_in[4];
    const float* b_ih0  = (const float*)d_in[5];
    const float* b_hh0  = (const float*)d_in[6];
    const float* w_ih1  = (const float*)d_in[7];
    const float* w_hh1  = (const float*)d_in[8];
    const float* b_ih1  = (const float*)d_in[9];
    const float* b_hh1  = (const float*)d_in[10];
    const float* w_ih2  = (const float*)d_in[11];
    const float* w_hh2  = (const float*)d_in[12];
    const float* b_ih2  = (const float*)d_in[13];
    const float* b_hh2  = (const float*)d_in[14];
    const float* w_fc   = (const float*)d_in[15];
    const float* b_fc   = (const float*)d_in[16];
    float* out = (float*)d_out;

    void *p_table, *p_xg, *p_h, *p_hlast, *p_order, *p_w0, *p_w1, *p_w2;
    cudaGetSymbolAddress(&p_table, g_table);
    cudaGetSymbolAddress(&p_xg,    g_xg);
    cudaGetSymbolAddress(&p_h,     g_h);
    cudaGetSymbolAddress(&p_hlast, g_hlast);
    cudaGetSymbolAddress(&p_order, g_order);
    cudaGetSymbolAddress(&p_w0,    g_w0p);
    cudaGetSymbolAddress(&p_w1,    g_w1p);
    cudaGetSymbolAddress(&p_w2,    g_w2p);
    float* table = (float*)p_table;
    float* xg    = (float*)p_xg;
    float* h     = (float*)p_h;
    float* hlast = (float*)p_hlast;
    int*   order = (int*)p_order;
    float* w0p   = (float*)p_w0;
    float* w1p   = (float*)p_w1;
    float* w2p   = (float*)p_w2;

    const int M = BN * TN;

    // 0) prep: sort + all weight padding (one launch)
    {
        int pad_total = G4P * KP0 + 2 * G4P * KP1;
        int blocks = 1 + (pad_total + 255) / 256;
        prep<<<blocks, 256>>>(lens, order, w_ih0, w0p, w_ih1, w1p, w_ih2, w2p);
    }

    // 1) vocab table GEMM: table = emb @ w_ih0^T + b_ih0 + b_hh0
    {
        dim3 grid(4, (VOCABN + 127) / 128);
        gemm_tf32<0><<<grid, 256>>>(emb, VOCABN, DIMN, DIMN, w0p, KP0,
                                    b_ih0, b_hh0, nullptr, table);
    }
    // 2) layer 0 scan (gathers table rows directly)
    lstm_scan<0><<<BN, 400>>>(table, x, lens, order, w_hh0, h, nullptr);

    // 3) layer 1 xg GEMM (+length tile-skip), then scan
    {
        dim3 grid(4, M / 128);
        gemm_tf32<1><<<grid, 256>>>(h, M, HN, HN, w1p, KP1,
                                    b_ih1, b_hh1, lens, xg);
    }
    lstm_scan<1><<<BN, 400>>>(xg, nullptr, lens, order, w_hh1, h, nullptr);

    // 4) layer 2 xg GEMM, then scan (hlast only)
    {
        dim3 grid(4, M / 128);
        gemm_tf32<1><<<grid, 256>>>(h, M, HN, HN, w2p, KP1,
                                    b_ih2, b_hh2, lens, xg);
    }
    lstm_scan<2><<<BN, 400>>>(xg, nullptr, lens, order, w_hh2, nullptr, hlast);

    // 5) head
    head_kernel<<<1, 256>>>(hlast, w_fc, b_fc, out);
}

// round 13
// speedup vs baseline: 1.1428x; 1.1428x over previous
#include <cuda_runtime.h>
#include <cstddef>
#include <cstdint>

#define VOCABN 50000
#define DIMN   300
#define HN     100
#define TN     512
#define BN     256
#define OUTN   3
#define G4     400   // 4*H
#define G4P    448   // padded N (7 tiles of 64)
#define KP0    304   // padded K for layer-0 table GEMM (emb K=300)
#define KP1    112   // padded K for xg GEMMs (h K=100)

// ---------------- scratch (static device globals; no allocation) ----------------
__device__ float g_table[(size_t)VOCABN * G4];
__device__ float g_xg[(size_t)BN * TN * G4];
__device__ float g_h[(size_t)BN * TN * HN];
__device__ float g_hlast[BN * HN];
__device__ int   g_order[BN];
__device__ float g_w0p[(size_t)G4P * KP0];
__device__ float g_w1p[(size_t)G4P * KP1];
__device__ float g_w2p[(size_t)G4P * KP1];

// ---------------- packed f32x2 helpers ----------------
typedef unsigned long long ull;

__device__ __forceinline__ ull pack2(float x, float y) {
    ull r;
    asm("mov.b64 %0, {%1, %2};" : "=l"(r) : "f"(x), "f"(y));
    return r;
}
__device__ __forceinline__ void unpack2(ull v, float& x, float& y) {
    asm("mov.b64 {%0, %1}, %2;" : "=f"(x), "=f"(y) : "l"(v));
}
__device__ __forceinline__ ull fma2(ull a, ull b, ull c) {
    ull d;
    asm("fma.rn.f32x2 %0, %1, %2, %3;" : "=l"(d) : "l"(a), "l"(b), "l"(c));
    return d;
}

// ---------------- tf32 helpers ----------------
__device__ __forceinline__ uint32_t f2tf(float x) {
    uint32_t r;
    asm("cvt.rna.tf32.f32 %0, %1;" : "=r"(r) : "f"(x));
    return r;
}
__device__ __forceinline__ void cvt_hl(float v, uint32_t& h, uint32_t& l) {
    h = f2tf(v);
    float lo = v - __uint_as_float(h);
    l = f2tf(lo);
}
__device__ __forceinline__ void mma_tf32(float (&d)[4], const uint32_t (&a)[4], const uint32_t (&b)[2]) {
    asm volatile(
        "mma.sync.aligned.m16n8k8.row.col.f32.tf32.tf32.f32 "
        "{%0,%1,%2,%3}, {%4,%5,%6,%7}, {%8,%9}, {%0,%1,%2,%3};"
        : "+f"(d[0]), "+f"(d[1]), "+f"(d[2]), "+f"(d[3])
        : "r"(a[0]), "r"(a[1]), "r"(a[2]), "r"(a[3]), "r"(b[0]), "r"(b[1]));
}

// ---------------- prep: sort + all weight padding in one launch ----------------
__global__ void prep(const int* __restrict__ lengths, int* __restrict__ order,
                     const float* __restrict__ w0, float* __restrict__ w0p,
                     const float* __restrict__ w1, float* __restrict__ w1p,
                     const float* __restrict__ w2s, float* __restrict__ w2p)
{
    const int bx = blockIdx.x;
    if (bx == 0) {
        __shared__ int ls[BN];
        int b = threadIdx.x;
        ls[b] = lengths[b];
        __syncthreads();
        int len = ls[b];
        int rank = 0;
#pragma unroll 8
        for (int jj = 0; jj < BN; jj++) {
            int lj = ls[jj];
            rank += (lj > len) || (lj == len && jj < b);
        }
        order[rank] = b;
        return;
    }
    int idx = (bx - 1) * 256 + threadIdx.x;
    const int n0 = G4P * KP0, n1 = G4P * KP1;
    if (idx < n0) {
        int r = idx / KP0, kk = idx % KP0;
        w0p[idx] = (r < G4 && kk < DIMN) ? w0[r * DIMN + kk] : 0.f;
        return;
    }
    idx -= n0;
    if (idx < n1) {
        int r = idx / KP1, kk = idx % KP1;
        w1p[idx] = (r < G4 && kk < HN) ? w1[r * HN + kk] : 0.f;
        return;
    }
    idx -= n1;
    if (idx < n1) {
        int r = idx / KP1, kk = idx % KP1;
        w2p[idx] = (r < G4 && kk < HN) ? w2s[r * HN + kk] : 0.f;
    }
}

// ---------------- 3xTF32 tensor-core GEMM (pitch-20, 128x64, 3 CTAs/SM) --------
template<int SKIP>
__global__ void __launch_bounds__(256, 3)
gemm_tf32(const float* __restrict__ A, int M, int Ks, int Kreal,
          const float* __restrict__ Bp, int Kp,
          const float* __restrict__ bias1, const float* __restrict__ bias2,
          const int* __restrict__ lengths, float* __restrict__ C)
{
    const int N = G4;
    const int m0 = blockIdx.y * 128;
    const int n0 = blockIdx.x * 64;
    if (SKIP) {
        int b  = m0 / TN;
        int t0 = m0 % TN;
        if (t0 >= lengths[b]) return;
    }

    __shared__ uint32_t As_hi[128 * 20], As_lo[128 * 20];
    __shared__ uint32_t Bs_hi[64 * 20],  Bs_lo[64 * 20];
    __shared__ float bias_s[64];

    const int tid  = threadIdx.x;
    const int wid  = tid >> 5;
    const int lane = tid & 31;
    const int wm   = wid & 3;
    const int wn   = wid >> 2;
    const int gid  = lane >> 2;
    const int tq   = lane & 3;

    if (tid < 64) {
        int n = n0 + tid;
        bias_s[tid] = (n < N) ? bias1[n] + bias2[n] : 0.f;
    }

    int mA[2], kqA[2];
#pragma unroll
    for (int i = 0; i < 2; i++) { int f = i * 256 + tid; mA[i] = f >> 2; kqA[i] = (f & 3) * 4; }
    const int nB = tid >> 2, kqB = (tid & 3) * 4;

    const float* aP[2];
#pragma unroll
    for (int i = 0; i < 2; i++) {
        int mg = m0 + mA[i]; if (mg > M - 1) mg = M - 1;
        aP[i] = A + (size_t)mg * Ks;
    }
    const float* bP = Bp + (size_t)(n0 + nB) * Kp;

    float acc[2][4][4];
#pragma unroll
    for (int i = 0; i < 2; i++)
#pragma unroll
        for (int j = 0; j < 4; j++)
#pragma unroll
            for (int q = 0; q < 4; q++) acc[i][j][q] = 0.f;

    const int kcl = Kreal - 4;
    float4 ra[2], rb;
#pragma unroll
    for (int i = 0; i < 2; i++) {
        int kk = kqA[i]; if (kk > kcl) kk = kcl;
        ra[i] = *reinterpret_cast<const float4*>(aP[i] + kk);
    }
    rb = *reinterpret_cast<const float4*>(bP + kqB);

    for (int k0 = 0; k0 < Kp; k0 += 16) {
#pragma unroll
        for (int i = 0; i < 2; i++) {
            uint32_t h0, l0, h1, l1, h2, l2, h3, l3;
            cvt_hl(ra[i].x, h0, l0); cvt_hl(ra[i].y, h1, l1);
            cvt_hl(ra[i].z, h2, l2); cvt_hl(ra[i].w, h3, l3);
            int off = mA[i] * 20 + kqA[i];
            *reinterpret_cast<uint4*>(&As_hi[off]) = make_uint4(h0, h1, h2, h3);
            *reinterpret_cast<uint4*>(&As_lo[off]) = make_uint4(l0, l1, l2, l3);
        }
        {
            uint32_t h0, l0, h1, l1, h2, l2, h3, l3;
            cvt_hl(rb.x, h0, l0); cvt_hl(rb.y, h1, l1);
            cvt_hl(rb.z, h2, l2); cvt_hl(rb.w, h3, l3);
            int off = nB * 20 + kqB;
            *reinterpret_cast<uint4*>(&Bs_hi[off]) = make_uint4(h0, h1, h2, h3);
            *reinterpret_cast<uint4*>(&Bs_lo[off]) = make_uint4(l0, l1, l2, l3);
        }
        __syncthreads();

        int k0n = k0 + 16;
        if (k0n < Kp) {
#pragma unroll
            for (int i = 0; i < 2; i++) {
                int kk = k0n + kqA[i]; if (kk > kcl) kk = kcl;
                ra[i] = *reinterpret_cast<const float4*>(aP[i] + kk);
            }
            rb = *reinterpret_cast<const float4*>(bP + k0n + kqB);
        }

#pragma unroll
        for (int ks = 0; ks < 2; ks++) {
            const int kb = ks * 8;
            uint32_t ah[2][4], al[2][4];
#pragma unroll
            for (int mf = 0; mf < 2; mf++) {
                int base = (wm * 32 + mf * 16 + gid) * 20 + kb + tq;
                ah[mf][0] = As_hi[base];              al[mf][0] = As_lo[base];
                ah[mf][1] = As_hi[base + 8 * 20];     al[mf][1] = As_lo[base + 8 * 20];
                ah[mf][2] = As_hi[base + 4];          al[mf][2] = As_lo[base + 4];
                ah[mf][3] = As_hi[base + 8 * 20 + 4]; al[mf][3] = As_lo[base + 8 * 20 + 4];
            }
            uint32_t bh[4][2], bl[4][2];
#pragma unroll
            for (int nf = 0; nf < 4; nf++) {
                int base = (wn * 32 + nf * 8 + gid) * 20 + kb + tq;
                bh[nf][0] = Bs_hi[base];     bl[nf][0] = Bs_lo[base];
                bh[nf][1] = Bs_hi[base + 4]; bl[nf][1] = Bs_lo[base + 4];
            }
#pragma unroll
            for (int mf = 0; mf < 2; mf++)
#pragma unroll
                for (int nf = 0; nf < 4; nf++) {
                    mma_tf32(acc[mf][nf], ah[mf], bh[nf]);
                    mma_tf32(acc[mf][nf], ah[mf], bl[nf]);
                    mma_tf32(acc[mf][nf], al[mf], bh[nf]);
                }
        }
        __syncthreads();
    }

#pragma unroll
    for (int mf = 0; mf < 2; mf++) {
#pragma unroll
        for (int nf = 0; nf < 4; nf++) {
            int row0 = m0 + wm * 32 + mf * 16 + gid;
            int cb   = wn * 32 + nf * 8 + 2 * tq;
            int col  = n0 + cb;
            if (col < N) {
                float b0v = bias_s[cb], b1v = bias_s[cb + 1];
                if (row0 < M) {
                    float2 v = make_float2(acc[mf][nf][0] + b0v, acc[mf][nf][1] + b1v);
                    *reinterpret_cast<float2*>(&C[(size_t)row0 * N + col]) = v;
                }
                int row1 = row0 + 8;
                if (row1 < M) {
                    float2 v = make_float2(acc[mf][nf][2] + b0v, acc[mf][nf][3] + b1v);
                    *reinterpret_cast<float2*>(&C[(size_t)row1 * N + col]) = v;
                }
            }
        }
    }
}

// ---------------- LSTM scan (round-11 winner, unchanged) ----------------
__device__ __forceinline__ float tanh_(float x) {
    return 2.f * __fdividef(1.f, 1.f + __expf(-2.f * x)) - 1.f;
}

// thread tid = j*4 + g : hidden unit j (0..99), gate g (0=i,1=f,2=g,3=o)
template<int MODE>
__global__ void __launch_bounds__(400, 1)
lstm_scan(const float* __restrict__ xg,
          const int* __restrict__ xtok,
          const int* __restrict__ lengths,
          const int* __restrict__ order,
          const float* __restrict__ w_hh,     // [400,100]
          float* __restrict__ h_out,          // [B,T,100]
          float* __restrict__ hlast)          // [B,100]
{
    const int b   = order[blockIdx.x];
    const int tid = threadIdx.x;
    const int j   = tid >> 2;
    const int g   = tid & 3;
    const int r   = g * 100 + j;

    __shared__ __align__(16) float h_s[2][104];
    __shared__ int idx_s[TN];

    const int len = lengths[b];

    if (MODE == 0) {
        for (int t = tid; t < TN; t += 400) idx_s[t] = xtok[b * TN + t];
    }

    ull w2[50];
    {
        const ull* wrow = reinterpret_cast<const ull*>(w_hh + r * 100);
#pragma unroll
        for (int q = 0; q < 50; q++) w2[q] = wrow[q];
    }

    if (tid < 100) h_s[0][tid] = 0.f;
    float c = 0.f;
    __syncthreads();

    const bool is_t = (g == 2);
    const bool gsel = (g & 2) != 0;

    const float* xp = (MODE == 0) ? nullptr : xg + ((size_t)b * TN) * G4 + r;
    float xg_next;
    if (MODE == 0) xg_next = xg[(size_t)idx_s[0] * G4 + r];
    else           xg_next = *xp;

    for (int t = 0; t < len; t++) {
        float xv = xg_next;
        if (t + 1 < len) {
            if (MODE == 0) {
                xg_next = xg[(size_t)idx_s[t + 1] * G4 + r];
            } else {
                xp += G4;
                xg_next = *xp;
            }
        }
        const ulonglong2* h2 = reinterpret_cast<const ulonglong2*>(h_s[t & 1]);

        ull acc0 = pack2(xv, 0.f);
        ull acc1 = 0ULL;
#pragma unroll
        for (int q = 0; q < 25; q++) {
            ulonglong2 hh = h2[q];
            acc0 = fma2(hh.x, w2[2 * q],     acc0);
            acc1 = fma2(hh.y, w2[2 * q + 1], acc1);
        }
        float a0, a1, a2, a3;
        unpack2(acc0, a0, a1);
        unpack2(acc1, a2, a3);
        float acc = (a0 + a1) + (a2 + a3);

        float z = is_t ? 2.f * acc : acc;
        float s = __fdividef(1.f, 1.f + __expf(-z));
        float gate = is_t ? (2.f * s - 1.f) : s;

        float v1 = __shfl_xor_sync(0xFFFFFFFFu, gate, 1);
        float pa = (g & 1) ? v1 : gate;
        float pb = (g & 1) ? gate : v1;
        float qa = __shfl_xor_sync(0xFFFFFFFFu, pa, 2);
        float qb = __shfl_xor_sync(0xFFFFFFFFu, pb, 2);
        float ig = gsel ? qa : pa;
        float gg = gsel ? pa : qa;
        float fg = gsel ? qb : pb;
        float og = gsel ? pb : qb;

        c = fg * c + ig * gg;
        float hn = og * tanh_(c);
        if (g == 0) {
            h_s[(t + 1) & 1][j] = hn;
            if (MODE != 2) h_out[((size_t)b * TN + t) * HN + j] = hn;
        }
        if (MODE == 2 && g == 0 && t == len - 1) hlast[b * HN + j] = hn;
        __syncthreads();
    }
}

// ---------------- head ----------------
__global__ void head_kernel(const float* __restrict__ hlast,
                            const float* __restrict__ w_fc,
                            const float* __restrict__ b_fc,
                            float* __restrict__ out)
{
    int b = blockIdx.x * blockDim.x + threadIdx.x;
    if (b >= BN) return;
#pragma unroll
    for (int o = 0; o < OUTN; o++) {
        float s = b_fc[o];
#pragma unroll
        for (int k = 0; k < HN; k++)
            s += hlast[b * HN + k] * w_fc[o * HN + k];
        out[b * OUTN + o] = s;
    }
}

// ---------------- launch (single stream) ----------------
extern "C" void kernel_launch(void* const* d_in, const int* in_sizes, int n_in,
                              void* d_out, int out_size)
{
    const int*   x      = (const int*)d_in[0];
    const int*   lens   = (const int*)d_in[1];
    const float* emb    = (const float*)d_in[2];
    const float* w_ih0  = (const float*)d_in[3];
    const float* w_hh0  = (const float*)d_in[4];
    const float* b_ih0  = (const float*)d_in[5];
    const float* b_hh0  = (const float*)d_in[6];
    const float* w_ih1  = (const float*)d_in[7];
    const float* w_hh1  = (const float*)d_in[8];
    const float* b_ih1  = (const float*)d_in[9];
    const float* b_hh1  = (const float*)d_in[10];
    const float* w_ih2  = (const float*)d_in[11];
    const float* w_hh2  = (const float*)d_in[12];
    const float* b_ih2  = (const float*)d_in[13];
    const float* b_hh2  = (const float*)d_in[14];
    const float* w_fc   = (const float*)d_in[15];
    const float* b_fc   = (const float*)d_in[16];
    float* out = (float*)d_out;

    void *p_table, *p_xg, *p_h, *p_hlast, *p_order, *p_w0, *p_w1, *p_w2;
    cudaGetSymbolAddress(&p_table, g_table);
    cudaGetSymbolAddress(&p_xg,    g_xg);
    cudaGetSymbolAddress(&p_h,     g_h);
    cudaGetSymbolAddress(&p_hlast, g_hlast);
    cudaGetSymbolAddress(&p_order, g_order);
    cudaGetSymbolAddress(&p_w0,    g_w0p);
    cudaGetSymbolAddress(&p_w1,    g_w1p);
    cudaGetSymbolAddress(&p_w2,    g_w2p);
    float* table = (float*)p_table;
    float* xg    = (float*)p_xg;
    float* h     = (float*)p_h;
    float* hlast = (float*)p_hlast;
    int*   order = (int*)p_order;
    float* w0p   = (float*)p_w0;
    float* w1p   = (float*)p_w1;
    float* w2p   = (float*)p_w2;

    const int M = BN * TN;

    // 0) prep: sort + all weight padding (one launch)
    {
        int pad_total = G4P * KP0 + 2 * G4P * KP1;
        int blocks = 1 + (pad_total + 255) / 256;
        prep<<<blocks, 256>>>(lens, order, w_ih0, w0p, w_ih1, w1p, w_ih2, w2p);
    }

    // 1) vocab table GEMM: table = emb @ w_ih0^T + b_ih0 + b_hh0
    {
        dim3 grid(7, (VOCABN + 127) / 128);
        gemm_tf32<0><<<grid, 256>>>(emb, VOCABN, DIMN, DIMN, w0p, KP0,
                                    b_ih0, b_hh0, nullptr, table);
    }
    // 2) layer 0 scan (gathers table rows directly)
    lstm_scan<0><<<BN, 400>>>(table, x, lens, order, w_hh0, h, nullptr);

    // 3) layer 1 xg GEMM (+length tile-skip), then scan
    {
        dim3 grid(7, M / 128);
        gemm_tf32<1><<<grid, 256>>>(h, M, HN, HN, w1p, KP1,
                                    b_ih1, b_hh1, lens, xg);
    }
    lstm_scan<1><<<BN, 400>>>(xg, nullptr, lens, order, w_hh1, h, nullptr);

    // 4) layer 2 xg GEMM, then scan (hlast only)
    {
        dim3 grid(7, M / 128);
        gemm_tf32<1><<<grid, 256>>>(h, M, HN, HN, w2p, KP1,
                                    b_ih2, b_hh2, lens, xg);
    }
    lstm_scan<2><<<BN, 400>>>(xg, nullptr, lens, order, w_hh2, nullptr, hlast);

    // 5) head
    head_kernel<<<1, 256>>>(hlast, w_fc, b_fc, out);
}

// round 14
// speedup vs baseline: 1.3575x; 1.1878x over previous
#include <cuda_runtime.h>
#include <cuda_bf16.h>
#include <cstddef>
#include <cstdint>

#define VOCABN 50000
#define DIMN   300
#define HN     100
#define TN     512
#define BN     256
#define OUTN   3
#define G4     400   // 4*H
#define G4P    448   // padded N (7 tiles of 64)
#define KP0    304   // padded K for layer-0 table GEMM (emb K=300)
#define KP1    112   // padded K for xg GEMMs (h K=100)

// ---------------- scratch (static device globals; no allocation) ----------------
__device__ float g_table[(size_t)VOCABN * G4];
__device__ float g_xg[(size_t)BN * TN * G4];
__device__ float g_h[(size_t)BN * TN * HN];
__device__ float g_hlast[BN * HN];
__device__ int   g_order[BN];
__device__ float g_w0p[(size_t)G4P * KP0];
__device__ float g_w1p[(size_t)G4P * KP1];
__device__ float g_w2p[(size_t)G4P * KP1];

// ---------------- packed f32x2 helpers ----------------
typedef unsigned long long ull;

__device__ __forceinline__ ull pack2(float x, float y) {
    ull r;
    asm("mov.b64 %0, {%1, %2};" : "=l"(r) : "f"(x), "f"(y));
    return r;
}
__device__ __forceinline__ void unpack2(ull v, float& x, float& y) {
    asm("mov.b64 {%0, %1}, %2;" : "=f"(x), "=f"(y) : "l"(v));
}
__device__ __forceinline__ ull fma2(ull a, ull b, ull c) {
    ull d;
    asm("fma.rn.f32x2 %0, %1, %2, %3;" : "=l"(d) : "l"(a), "l"(b), "l"(c));
    return d;
}

// ---------------- bf16 split helpers ----------------
// x = hi + lo, both bf16; hi*hi + hi*lo + lo*hi reproduces x*y to ~2^-17 rel.
__device__ __forceinline__ void cvt_bf_hl(float x, uint32_t& h, uint32_t& l) {
    __nv_bfloat16 hb = __float2bfloat16_rn(x);
    float lr = x - __bfloat162float(hb);
    __nv_bfloat16 lb = __float2bfloat16_rn(lr);
    h = (uint32_t)*reinterpret_cast<unsigned short*>(&hb);
    l = (uint32_t)*reinterpret_cast<unsigned short*>(&lb);
}
__device__ __forceinline__ void mma_bf16(float (&d)[4], const uint32_t (&a)[4], const uint32_t (&b)[2]) {
    asm volatile(
        "mma.sync.aligned.m16n8k16.row.col.f32.bf16.bf16.f32 "
        "{%0,%1,%2,%3}, {%4,%5,%6,%7}, {%8,%9}, {%0,%1,%2,%3};"
        : "+f"(d[0]), "+f"(d[1]), "+f"(d[2]), "+f"(d[3])
        : "r"(a[0]), "r"(a[1]), "r"(a[2]), "r"(a[3]), "r"(b[0]), "r"(b[1]));
}

// ---------------- prep: sort + all weight padding in one launch ----------------
__global__ void prep(const int* __restrict__ lengths, int* __restrict__ order,
                     const float* __restrict__ w0, float* __restrict__ w0p,
                     const float* __restrict__ w1, float* __restrict__ w1p,
                     const float* __restrict__ w2s, float* __restrict__ w2p)
{
    const int bx = blockIdx.x;
    if (bx == 0) {
        __shared__ int ls[BN];
        int b = threadIdx.x;
        ls[b] = lengths[b];
        __syncthreads();
        int len = ls[b];
        int rank = 0;
#pragma unroll 8
        for (int jj = 0; jj < BN; jj++) {
            int lj = ls[jj];
            rank += (lj > len) || (lj == len && jj < b);
        }
        order[rank] = b;
        return;
    }
    int idx = (bx - 1) * 256 + threadIdx.x;
    const int n0 = G4P * KP0, n1 = G4P * KP1;
    if (idx < n0) {
        int r = idx / KP0, kk = idx % KP0;
        w0p[idx] = (r < G4 && kk < DIMN) ? w0[r * DIMN + kk] : 0.f;
        return;
    }
    idx -= n0;
    if (idx < n1) {
        int r = idx / KP1, kk = idx % KP1;
        w1p[idx] = (r < G4 && kk < HN) ? w1[r * HN + kk] : 0.f;
        return;
    }
    idx -= n1;
    if (idx < n1) {
        int r = idx / KP1, kk = idx % KP1;
        w2p[idx] = (r < G4 && kk < HN) ? w2s[r * HN + kk] : 0.f;
    }
}

// ---------------- 3xBF16 tensor-core GEMM (m16n8k16, pitch-20, 128x64) --------
// C[m,n] = sum_k A[m,k]*Bp[n,k] + bias1[n] + bias2[n],  N fixed = 400.
// smem row (pitch 20 words): words 0-7 = hi bf16x2 pairs (k/2), 8-15 = lo pairs.
template<int SKIP>
__global__ void __launch_bounds__(256, 3)
gemm_bf16(const float* __restrict__ A, int M, int Ks, int Kreal,
          const float* __restrict__ Bp, int Kp,
          const float* __restrict__ bias1, const float* __restrict__ bias2,
          const int* __restrict__ lengths, float* __restrict__ C)
{
    const int N = G4;
    const int m0 = blockIdx.y * 128;
    const int n0 = blockIdx.x * 64;
    if (SKIP) {
        int b  = m0 / TN;
        int t0 = m0 % TN;
        if (t0 >= lengths[b]) return;
    }

    __shared__ uint32_t As[128 * 20];
    __shared__ uint32_t Bs[64 * 20];
    __shared__ float bias_s[64];

    const int tid  = threadIdx.x;
    const int wid  = tid >> 5;
    const int lane = tid & 31;
    const int wm   = wid & 3;
    const int wn   = wid >> 2;
    const int gid  = lane >> 2;
    const int tq   = lane & 3;

    if (tid < 64) {
        int n = n0 + tid;
        bias_s[tid] = (n < N) ? bias1[n] + bias2[n] : 0.f;
    }

    int mA[2], kqA[2];
#pragma unroll
    for (int i = 0; i < 2; i++) { int f = i * 256 + tid; mA[i] = f >> 2; kqA[i] = (f & 3) * 4; }
    const int nB = tid >> 2, kqB = (tid & 3) * 4;

    const float* aP[2];
#pragma unroll
    for (int i = 0; i < 2; i++) {
        int mg = m0 + mA[i]; if (mg > M - 1) mg = M - 1;
        aP[i] = A + (size_t)mg * Ks;
    }
    const float* bP = Bp + (size_t)(n0 + nB) * Kp;

    float acc[2][4][4];
#pragma unroll
    for (int i = 0; i < 2; i++)
#pragma unroll
        for (int j = 0; j < 4; j++)
#pragma unroll
            for (int q = 0; q < 4; q++) acc[i][j][q] = 0.f;

    const int kcl = Kreal - 4;
    float4 ra[2], rb;
#pragma unroll
    for (int i = 0; i < 2; i++) {
        int kk = kqA[i]; if (kk > kcl) kk = kcl;
        ra[i] = *reinterpret_cast<const float4*>(aP[i] + kk);
    }
    rb = *reinterpret_cast<const float4*>(bP + kqB);

    for (int k0 = 0; k0 < Kp; k0 += 16) {
        // ---- stage regs -> smem (split to bf16 hi/lo pairs) ----
#pragma unroll
        for (int i = 0; i < 2; i++) {
            uint32_t h0, l0, h1, l1, h2, l2, h3, l3;
            cvt_bf_hl(ra[i].x, h0, l0); cvt_bf_hl(ra[i].y, h1, l1);
            cvt_bf_hl(ra[i].z, h2, l2); cvt_bf_hl(ra[i].w, h3, l3);
            int off = mA[i] * 20 + (kqA[i] >> 1);
            *reinterpret_cast<uint2*>(&As[off])     = make_uint2(h0 | (h1 << 16), h2 | (h3 << 16));
            *reinterpret_cast<uint2*>(&As[off + 8]) = make_uint2(l0 | (l1 << 16), l2 | (l3 << 16));
        }
        {
            uint32_t h0, l0, h1, l1, h2, l2, h3, l3;
            cvt_bf_hl(rb.x, h0, l0); cvt_bf_hl(rb.y, h1, l1);
            cvt_bf_hl(rb.z, h2, l2); cvt_bf_hl(rb.w, h3, l3);
            int off = nB * 20 + (kqB >> 1);
            *reinterpret_cast<uint2*>(&Bs[off])     = make_uint2(h0 | (h1 << 16), h2 | (h3 << 16));
            *reinterpret_cast<uint2*>(&Bs[off + 8]) = make_uint2(l0 | (l1 << 16), l2 | (l3 << 16));
        }
        __syncthreads();

        // ---- prefetch next stage ----
        int k0n = k0 + 16;
        if (k0n < Kp) {
#pragma unroll
            for (int i = 0; i < 2; i++) {
                int kk = k0n + kqA[i]; if (kk > kcl) kk = kcl;
                ra[i] = *reinterpret_cast<const float4*>(aP[i] + kk);
            }
            rb = *reinterpret_cast<const float4*>(bP + k0n + kqB);
        }

        // ---- one k16 mma step ----
        {
            uint32_t ah[2][4], al[2][4];
#pragma unroll
            for (int mf = 0; mf < 2; mf++) {
                int base = (wm * 32 + mf * 16 + gid) * 20 + tq;
                ah[mf][0] = As[base];              al[mf][0] = As[base + 8];
                ah[mf][1] = As[base + 8 * 20];     al[mf][1] = As[base + 8 * 20 + 8];
                ah[mf][2] = As[base + 4];          al[mf][2] = As[base + 12];
                ah[mf][3] = As[base + 8 * 20 + 4]; al[mf][3] = As[base + 8 * 20 + 12];
            }
            uint32_t bh[4][2], bl[4][2];
#pragma unroll
            for (int nf = 0; nf < 4; nf++) {
                int base = (wn * 32 + nf * 8 + gid) * 20 + tq;
                bh[nf][0] = Bs[base];     bl[nf][0] = Bs[base + 8];
                bh[nf][1] = Bs[base + 4]; bl[nf][1] = Bs[base + 12];
            }
#pragma unroll
            for (int mf = 0; mf < 2; mf++)
#pragma unroll
                for (int nf = 0; nf < 4; nf++) {
                    mma_bf16(acc[mf][nf], ah[mf], bh[nf]);
                    mma_bf16(acc[mf][nf], ah[mf], bl[nf]);
                    mma_bf16(acc[mf][nf], al[mf], bh[nf]);
                }
        }
        __syncthreads();
    }

#pragma unroll
    for (int mf = 0; mf < 2; mf++) {
#pragma unroll
        for (int nf = 0; nf < 4; nf++) {
            int row0 = m0 + wm * 32 + mf * 16 + gid;
            int cb   = wn * 32 + nf * 8 + 2 * tq;
            int col  = n0 + cb;
            if (col < N) {
                float b0v = bias_s[cb], b1v = bias_s[cb + 1];
                if (row0 < M) {
                    float2 v = make_float2(acc[mf][nf][0] + b0v, acc[mf][nf][1] + b1v);
                    *reinterpret_cast<float2*>(&C[(size_t)row0 * N + col]) = v;
                }
                int row1 = row0 + 8;
                if (row1 < M) {
                    float2 v = make_float2(acc[mf][nf][2] + b0v, acc[mf][nf][3] + b1v);
                    *reinterpret_cast<float2*>(&C[(size_t)row1 * N + col]) = v;
                }
            }
        }
    }
}

// ---------------- LSTM scan (round-11 winner, unchanged) ----------------
__device__ __forceinline__ float tanh_(float x) {
    return 2.f * __fdividef(1.f, 1.f + __expf(-2.f * x)) - 1.f;
}

// thread tid = j*4 + g : hidden unit j (0..99), gate g (0=i,1=f,2=g,3=o)
template<int MODE>
__global__ void __launch_bounds__(400, 1)
lstm_scan(const float* __restrict__ xg,
          const int* __restrict__ xtok,
          const int* __restrict__ lengths,
          const int* __restrict__ order,
          const float* __restrict__ w_hh,     // [400,100]
          float* __restrict__ h_out,          // [B,T,100]
          float* __restrict__ hlast)          // [B,100]
{
    const int b   = order[blockIdx.x];
    const int tid = threadIdx.x;
    const int j   = tid >> 2;
    const int g   = tid & 3;
    const int r   = g * 100 + j;

    __shared__ __align__(16) float h_s[2][104];
    __shared__ int idx_s[TN];

    const int len = lengths[b];

    if (MODE == 0) {
        for (int t = tid; t < TN; t += 400) idx_s[t] = xtok[b * TN + t];
    }

    ull w2[50];
    {
        const ull* wrow = reinterpret_cast<const ull*>(w_hh + r * 100);
#pragma unroll
        for (int q = 0; q < 50; q++) w2[q] = wrow[q];
    }

    if (tid < 100) h_s[0][tid] = 0.f;
    float c = 0.f;
    __syncthreads();

    const bool is_t = (g == 2);
    const bool gsel = (g & 2) != 0;

    const float* xp = (MODE == 0) ? nullptr : xg + ((size_t)b * TN) * G4 + r;
    float xg_next;
    if (MODE == 0) xg_next = xg[(size_t)idx_s[0] * G4 + r];
    else           xg_next = *xp;

    for (int t = 0; t < len; t++) {
        float xv = xg_next;
        if (t + 1 < len) {
            if (MODE == 0) {
                xg_next = xg[(size_t)idx_s[t + 1] * G4 + r];
            } else {
                xp += G4;
                xg_next = *xp;
            }
        }
        const ulonglong2* h2 = reinterpret_cast<const ulonglong2*>(h_s[t & 1]);

        ull acc0 = pack2(xv, 0.f);
        ull acc1 = 0ULL;
#pragma unroll
        for (int q = 0; q < 25; q++) {
            ulonglong2 hh = h2[q];
            acc0 = fma2(hh.x, w2[2 * q],     acc0);
            acc1 = fma2(hh.y, w2[2 * q + 1], acc1);
        }
        float a0, a1, a2, a3;
        unpack2(acc0, a0, a1);
        unpack2(acc1, a2, a3);
        float acc = (a0 + a1) + (a2 + a3);

        float z = is_t ? 2.f * acc : acc;
        float s = __fdividef(1.f, 1.f + __expf(-z));
        float gate = is_t ? (2.f * s - 1.f) : s;

        float v1 = __shfl_xor_sync(0xFFFFFFFFu, gate, 1);
        float pa = (g & 1) ? v1 : gate;
        float pb = (g & 1) ? gate : v1;
        float qa = __shfl_xor_sync(0xFFFFFFFFu, pa, 2);
        float qb = __shfl_xor_sync(0xFFFFFFFFu, pb, 2);
        float ig = gsel ? qa : pa;
        float gg = gsel ? pa : qa;
        float fg = gsel ? qb : pb;
        float og = gsel ? pb : qb;

        c = fg * c + ig * gg;
        float hn = og * tanh_(c);
        if (g == 0) {
            h_s[(t + 1) & 1][j] = hn;
            if (MODE != 2) h_out[((size_t)b * TN + t) * HN + j] = hn;
        }
        if (MODE == 2 && g == 0 && t == len - 1) hlast[b * HN + j] = hn;
        __syncthreads();
    }
}

// ---------------- head ----------------
__global__ void head_kernel(const float* __restrict__ hlast,
                            const float* __restrict__ w_fc,
                            const float* __restrict__ b_fc,
                            float* __restrict__ out)
{
    int b = blockIdx.x * blockDim.x + threadIdx.x;
    if (b >= BN) return;
#pragma unroll
    for (int o = 0; o < OUTN; o++) {
        float s = b_fc[o];
#pragma unroll
        for (int k = 0; k < HN; k++)
            s += hlast[b * HN + k] * w_fc[o * HN + k];
        out[b * OUTN + o] = s;
    }
}

// ---------------- launch (single stream) ----------------
extern "C" void kernel_launch(void* const* d_in, const int* in_sizes, int n_in,
                              void* d_out, int out_size)
{
    const int*   x      = (const int*)d_in[0];
    const int*   lens   = (const int*)d_in[1];
    const float* emb    = (const float*)d_in[2];
    const float* w_ih0  = (const float*)d_in[3];
    const float* w_hh0  = (const float*)d_in[4];
    const float* b_ih0  = (const float*)d_in[5];
    const float* b_hh0  = (const float*)d_in[6];
    const float* w_ih1  = (const float*)d_in[7];
    const float* w_hh1  = (const float*)d_in[8];
    const float* b_ih1  = (const float*)d_in[9];
    const float* b_hh1  = (const float*)d_in[10];
    const float* w_ih2  = (const float*)d_in[11];
    const float* w_hh2  = (const float*)d_in[12];
    const float* b_ih2  = (const float*)d_in[13];
    const float* b_hh2  = (const float*)d_in[14];
    const float* w_fc   = (const float*)d_in[15];
    const float* b_fc   = (const float*)d_in[16];
    float* out = (float*)d_out;

    void *p_table, *p_xg, *p_h, *p_hlast, *p_order, *p_w0, *p_w1, *p_w2;
    cudaGetSymbolAddress(&p_table, g_table);
    cudaGetSymbolAddress(&p_xg,    g_xg);
    cudaGetSymbolAddress(&p_h,     g_h);
    cudaGetSymbolAddress(&p_hlast, g_hlast);
    cudaGetSymbolAddress(&p_order, g_order);
    cudaGetSymbolAddress(&p_w0,    g_w0p);
    cudaGetSymbolAddress(&p_w1,    g_w1p);
    cudaGetSymbolAddress(&p_w2,    g_w2p);
    float* table = (float*)p_table;
    float* xg    = (float*)p_xg;
    float* h     = (float*)p_h;
    float* hlast = (float*)p_hlast;
    int*   order = (int*)p_order;
    float* w0p   = (float*)p_w0;
    float* w1p   = (float*)p_w1;
    float* w2p   = (float*)p_w2;

    const int M = BN * TN;

    // 0) prep: sort + all weight padding (one launch)
    {
        int pad_total = G4P * KP0 + 2 * G4P * KP1;
        int blocks = 1 + (pad_total + 255) / 256;
        prep<<<blocks, 256>>>(lens, order, w_ih0, w0p, w_ih1, w1p, w_ih2, w2p);
    }

    // 1) vocab table GEMM: table = emb @ w_ih0^T + b_ih0 + b_hh0
    {
        dim3 grid(7, (VOCABN + 127) / 128);
        gemm_bf16<0><<<grid, 256>>>(emb, VOCABN, DIMN, DIMN, w0p, KP0,
                                    b_ih0, b_hh0, nullptr, table);
    }
    // 2) layer 0 scan (gathers table rows directly)
    lstm_scan<0><<<BN, 400>>>(table, x, lens, order, w_hh0, h, nullptr);

    // 3) layer 1 xg GEMM (+length tile-skip), then scan
    {
        dim3 grid(7, M / 128);
        gemm_bf16<1><<<grid, 256>>>(h, M, HN, HN, w1p, KP1,
                                    b_ih1, b_hh1, lens, xg);
    }
    lstm_scan<1><<<BN, 400>>>(xg, nullptr, lens, order, w_hh1, h, nullptr);

    // 4) layer 2 xg GEMM, then scan (hlast only)
    {
        dim3 grid(7, M / 128);
        gemm_bf16<1><<<grid, 256>>>(h, M, HN, HN, w2p, KP1,
                                    b_ih2, b_hh2, lens, xg);
    }
    lstm_scan<2><<<BN, 400>>>(xg, nullptr, lens, order, w_hh2, nullptr, hlast);

    // 5) head
    head_kernel<<<1, 256>>>(hlast, w_fc, b_fc, out);
}